// round 2
// baseline (speedup 1.0000x reference)
#include <cuda_runtime.h>
#include <cstdint>

#define B_   16
#define S_   2048
#define D_   1024
#define H_   1024
#define NOUT (3 * H_)     // 3072
#define KDIM (2 * D_)     // 2048
#define MDIM (S_ * B_)    // 32768

// Scratch for Y = source @ W^T + b   (S, B, 3H) fp32 = 402 MB
__device__ float g_Y[(size_t)S_ * B_ * NOUT];

// ---------------------------------------------------------------------------
// GEMM: Y[m, n] = sum_k A[m,k] * W[n,k] + bias[n]
//   m = s*B + b ;  A[m, k] = X[b, s, k]        (k <  D)
//                  A[m, k] = X[b, s-1, k-D]    (k >= D, zero if s == 0)
// TF32 mma.sync m16n8k8, 128x128x16 block tile, 2-stage cp.async pipeline.
// ---------------------------------------------------------------------------

#define BM 128
#define BN 128
#define BK 16
#define ASTRIDE 20   // 16 + 4 pad -> conflict-free mma fragment LDS

__device__ __forceinline__ void cp_async16(void* smem, const void* gptr, int src_bytes) {
    uint32_t s = (uint32_t)__cvta_generic_to_shared(smem);
    asm volatile("cp.async.cg.shared.global [%0], [%1], 16, %2;\n"
                 :: "r"(s), "l"(gptr), "r"(src_bytes));
}
__device__ __forceinline__ void cp_commit() {
    asm volatile("cp.async.commit_group;\n");
}
template <int N>
__device__ __forceinline__ void cp_wait() {
    asm volatile("cp.async.wait_group %0;\n" :: "n"(N));
}

__device__ __forceinline__ uint32_t f2tf32(float x) {
    uint32_t y;
    asm("cvt.rna.tf32.f32 %0, %1;\n" : "=r"(y) : "f"(x));
    return y;
}

__device__ __forceinline__ void mma_tf32(float& d0, float& d1, float& d2, float& d3,
                                         uint32_t a0, uint32_t a1, uint32_t a2, uint32_t a3,
                                         uint32_t b0, uint32_t b1) {
    asm volatile(
        "mma.sync.aligned.m16n8k8.row.col.f32.tf32.tf32.f32 "
        "{%0,%1,%2,%3}, {%4,%5,%6,%7}, {%8,%9}, {%0,%1,%2,%3};\n"
        : "+f"(d0), "+f"(d1), "+f"(d2), "+f"(d3)
        : "r"(a0), "r"(a1), "r"(a2), "r"(a3), "r"(b0), "r"(b1));
}

__global__ __launch_bounds__(256, 1)
void qrnn_gemm(const float* __restrict__ X, const float* __restrict__ W,
               const float* __restrict__ bias)
{
    __shared__ float sA[2][BM * ASTRIDE];
    __shared__ float sB[2][BN * ASTRIDE];

    const int tid  = threadIdx.x;
    const int warp = tid >> 5;
    const int lane = tid & 31;
    const int m0 = blockIdx.y * BM;
    const int n0 = blockIdx.x * BN;
    // 2 warps along M x 4 along N; warp tile 64x32
    const int wm = (warp >> 2) * 64;
    const int wn = (warp & 3) * 32;

    float acc[4][4][4];
#pragma unroll
    for (int mt = 0; mt < 4; mt++)
#pragma unroll
        for (int nt = 0; nt < 4; nt++)
#pragma unroll
            for (int r = 0; r < 4; r++) acc[mt][nt][r] = 0.f;

    // -- stage loader: 512 16B chunks per tile, 2 per thread for A and B each
    auto load_stage = [&](int st, int k0) {
#pragma unroll
        for (int i = 0; i < 2; i++) {
            int c   = tid + i * 256;
            int row = c >> 2;
            int kc  = (c & 3) * 4;
            int m = m0 + row;
            int s = m >> 4;        // B_ = 16
            int b = m & 15;
            int k = k0 + kc;
            const float* src;
            int sz = 16;
            if (k < D_) {
                src = X + ((size_t)b * S_ + s) * D_ + k;
            } else if (s > 0) {
                src = X + ((size_t)b * S_ + (s - 1)) * D_ + (k - D_);
            } else {
                src = X;           // dummy, zero-filled
                sz = 0;
            }
            cp_async16(&sA[st][row * ASTRIDE + kc], src, sz);
        }
#pragma unroll
        for (int i = 0; i < 2; i++) {
            int c   = tid + i * 256;
            int row = c >> 2;
            int kc  = (c & 3) * 4;
            int n   = n0 + row;
            cp_async16(&sB[st][row * ASTRIDE + kc],
                       W + (size_t)n * KDIM + k0 + kc, 16);
        }
    };

    load_stage(0, 0);
    cp_commit();

    const int NK = KDIM / BK;   // 128
    const int r_  = lane >> 2;
    const int cq  = lane & 3;

    for (int it = 0; it < NK; ++it) {
        cp_wait<0>();
        __syncthreads();

        int kn = (it + 1) * BK;
        if (kn < KDIM) load_stage((it + 1) & 1, kn);
        cp_commit();

        const int st = it & 1;
#pragma unroll
        for (int ks = 0; ks < BK; ks += 8) {
            uint32_t af[4][4], bf[4][2];
#pragma unroll
            for (int mt = 0; mt < 4; mt++) {
                const float* base = &sA[st][(wm + mt * 16 + r_) * ASTRIDE + ks + cq];
                af[mt][0] = f2tf32(base[0]);
                af[mt][1] = f2tf32(base[8 * ASTRIDE]);
                af[mt][2] = f2tf32(base[4]);
                af[mt][3] = f2tf32(base[8 * ASTRIDE + 4]);
            }
#pragma unroll
            for (int nt = 0; nt < 4; nt++) {
                const float* bb = &sB[st][(wn + nt * 8 + r_) * ASTRIDE + ks + cq];
                bf[nt][0] = f2tf32(bb[0]);
                bf[nt][1] = f2tf32(bb[4]);
            }
#pragma unroll
            for (int mt = 0; mt < 4; mt++)
#pragma unroll
                for (int nt = 0; nt < 4; nt++)
                    mma_tf32(acc[mt][nt][0], acc[mt][nt][1], acc[mt][nt][2], acc[mt][nt][3],
                             af[mt][0], af[mt][1], af[mt][2], af[mt][3],
                             bf[nt][0], bf[nt][1]);
        }
    }

    // epilogue: bias add, write Y
#pragma unroll
    for (int mt = 0; mt < 4; mt++) {
        int mrow = m0 + wm + mt * 16 + r_;
#pragma unroll
        for (int nt = 0; nt < 4; nt++) {
            int n = n0 + wn + nt * 8 + 2 * cq;
            float2 bb = *(const float2*)&bias[n];
            float2 v0 = make_float2(acc[mt][nt][0] + bb.x, acc[mt][nt][1] + bb.y);
            float2 v1 = make_float2(acc[mt][nt][2] + bb.x, acc[mt][nt][3] + bb.y);
            *(float2*)&g_Y[(size_t)mrow * NOUT + n]       = v0;
            *(float2*)&g_Y[(size_t)(mrow + 8) * NOUT + n] = v1;
        }
    }
}

// ---------------------------------------------------------------------------
// Recurrence + activations + output gate.
// One thread per (b, h) channel; sequential over S with unrolled independent
// loads (activations don't depend on the carried c).
// out[0 : S*B*H]           = Hout (S,B,H)
// out[S*B*H : S*B*H + B*H] = c_last
// ---------------------------------------------------------------------------
__device__ __forceinline__ float sigmoidf_(float x) {
    return 1.f / (1.f + __expf(-x));
}

__global__ __launch_bounds__(128)
void qrnn_scan(const float* __restrict__ hidden, float* __restrict__ out)
{
    int idx = blockIdx.x * blockDim.x + threadIdx.x;   // 0 .. B*H-1
    int b = idx >> 10;     // H = 1024
    int h = idx & 1023;

    float c = hidden[idx];
    const float* Yp = g_Y + (size_t)b * NOUT + h;
    float* Op = out + (size_t)b * H_ + h;

#pragma unroll 4
    for (int s = 0; s < S_; s++) {
        const float* p = Yp + (size_t)s * (B_ * NOUT);
        float zr = p[0];
        float fr = p[H_];
        float orr = p[2 * H_];
        float z = tanhf(zr);
        float f = sigmoidf_(fr);
        float o = sigmoidf_(orr);
        c = fmaf(f, z - c, c);
        Op[(size_t)s * (B_ * H_)] = o * c;
    }
    out[(size_t)S_ * B_ * H_ + idx] = c;   // c_last
}

// ---------------------------------------------------------------------------
extern "C" void kernel_launch(void* const* d_in, const int* in_sizes, int n_in,
                              void* d_out, int out_size)
{
    const float* X      = (const float*)d_in[0];
    const float* hidden = (const float*)d_in[1];
    const float* W      = (const float*)d_in[2];
    const float* bias   = (const float*)d_in[3];
    float* out = (float*)d_out;

    dim3 grid(NOUT / BN, MDIM / BM);   // (24, 256); n fastest -> A-tile L2 reuse
    qrnn_gemm<<<grid, 256>>>(X, W, bias);
    qrnn_scan<<<(B_ * H_) / 128, 128>>>(hidden, out);
}

// round 4
// speedup vs baseline: 3.3606x; 3.3606x over previous
#include <cuda_runtime.h>
#include <cstdint>

#define B_   16
#define S_   2048
#define D_   1024
#define H_   1024
#define NOUT 3072          // 3H
#define KDIM 2048          // 2D
#define MDIM 32768         // S*B
#define BH   16384         // B*H
#define NCH  32            // scan chunks
#define CHS  64            // steps per chunk (S/NCH)

// tcgen05 is an arch-SPECIFIC (sm_103a) feature set: only emit it in passes
// that carry the 'a' suffix. Other passes get a legacy mma.sync fallback.
#if defined(__CUDA_ARCH__) && (defined(__CUDA_ARCH_FEAT_SM103_ALL) || defined(__CUDA_ARCH_FEAT_SM100_ALL))
#define QRNN_TC 1
#else
#define QRNN_TC 0
#endif

// ---------------- scratch (device globals; no allocs allowed) ----------------
__device__ float g_Y [(size_t)MDIM * NOUT];       // activated gates (s,b,3H)
__device__ float g_Xr[(size_t)B_ * S_ * D_];      // tf32-rounded X
__device__ float g_Wr[(size_t)NOUT * KDIM];       // tf32-rounded W
__device__ float g_cA[NCH * BH];                  // chunk-local scan value (c_in=0)
__device__ float g_cP[NCH * BH];                  // chunk decay product
__device__ float g_cin[NCH * BH];                 // per-chunk incoming carry

// ---------------- common PTX helpers (legal on base sm_103) ----------------
__device__ __forceinline__ uint32_t smem_u32(const void* p) {
    return (uint32_t)__cvta_generic_to_shared(p);
}
__device__ __forceinline__ void cp_async16(uint32_t saddr, const void* g, int sz) {
    asm volatile("cp.async.cg.shared.global [%0], [%1], 16, %2;\n"
                 :: "r"(saddr), "l"(g), "r"(sz));
}
__device__ __forceinline__ void cp_commit() {
    asm volatile("cp.async.commit_group;\n");
}
template <int N> __device__ __forceinline__ void cp_wait() {
    asm volatile("cp.async.wait_group %0;\n" :: "n"(N));
}
__device__ __forceinline__ bool elect_one() {
    uint32_t pred;
    asm volatile("{\n\t.reg .pred p;\n\telect.sync _|p, 0xFFFFFFFF;\n\t"
                 "selp.b32 %0, 1, 0, p;\n\t}" : "=r"(pred));
    return pred != 0;
}
__device__ __forceinline__ void mbar_init(uint32_t a, uint32_t cnt) {
    asm volatile("mbarrier.init.shared.b64 [%0], %1;" :: "r"(a), "r"(cnt) : "memory");
}
__device__ __forceinline__ void mbar_wait(uint32_t a, uint32_t parity) {
    asm volatile(
        "{\n\t.reg .pred P1;\n\t"
        "WL_%=:\n\t"
        "mbarrier.try_wait.parity.acquire.cta.shared::cta.b64 P1, [%0], %1, 0x989680;\n\t"
        "@P1 bra.uni WD_%=;\n\t"
        "bra.uni WL_%=;\n\t"
        "WD_%=:\n\t}"
        :: "r"(a), "r"(parity) : "memory");
}

// ---------------- tcgen05 helpers (guarded) ----------------
#if QRNN_TC
// K-major SW128 SMEM matrix descriptor (layout=2, version=1, SBO=64, LBO=1)
__device__ __forceinline__ uint64_t make_desc(uint32_t addr) {
    const uint64_t base = (2ull << 61) | (1ull << 46) | (64ull << 32) | (1ull << 16);
    return base | (uint64_t)((addr >> 4) & 0x3FFF);
}
__device__ __forceinline__ void mma_tf32_ss(uint32_t d, uint64_t ad, uint64_t bd,
                                            uint32_t idesc, uint32_t en) {
    asm volatile(
        "{\n\t.reg .pred p;\n\tsetp.ne.u32 p, %4, 0;\n\t"
        "tcgen05.mma.cta_group::1.kind::tf32 [%0], %1, %2, %3, {%5,%5,%5,%5}, p;\n\t}"
        :: "r"(d), "l"(ad), "l"(bd), "r"(idesc), "r"(en), "r"(0u) : "memory");
}
#endif

// legacy mma.sync tf32 (valid everywhere)
__device__ __forceinline__ void mma_tf32_legacy(float& d0, float& d1, float& d2, float& d3,
                                                uint32_t a0, uint32_t a1, uint32_t a2, uint32_t a3,
                                                uint32_t b0, uint32_t b1) {
    asm volatile(
        "mma.sync.aligned.m16n8k8.row.col.f32.tf32.tf32.f32 "
        "{%0,%1,%2,%3}, {%4,%5,%6,%7}, {%8,%9}, {%0,%1,%2,%3};\n"
        : "+f"(d0), "+f"(d1), "+f"(d2), "+f"(d3)
        : "r"(a0), "r"(a1), "r"(a2), "r"(a3), "r"(b0), "r"(b1));
}

// ---------------- input rounding to tf32 (RNA) ----------------
__device__ __forceinline__ float tf32r(float x) {
    uint32_t y;
    asm("cvt.rna.tf32.f32 %0, %1;" : "=r"(y) : "f"(x));
    return __uint_as_float(y);
}
__global__ __launch_bounds__(256) void round_x(const float4* __restrict__ in) {
    const int n4 = (B_ * S_ * D_) / 4;
    float4* out = (float4*)g_Xr;
    int i = blockIdx.x * 256 + threadIdx.x;
    int stride = gridDim.x * 256;
    for (; i < n4; i += stride) {
        float4 v = in[i];
        out[i] = make_float4(tf32r(v.x), tf32r(v.y), tf32r(v.z), tf32r(v.w));
    }
}
__global__ __launch_bounds__(256) void round_w(const float4* __restrict__ in) {
    const int n4 = (NOUT * KDIM) / 4;
    float4* out = (float4*)g_Wr;
    int i = blockIdx.x * 256 + threadIdx.x;
    int stride = gridDim.x * 256;
    for (; i < n4; i += stride) {
        float4 v = in[i];
        out[i] = make_float4(tf32r(v.x), tf32r(v.y), tf32r(v.z), tf32r(v.w));
    }
}

// ---------------- GEMM: Y = act( A @ W^T + bias ) ----------------
//   m = s*16+b; A[m,k] = Xr[b,s,k] (k<D) | Xr[b,s-1,k-D] (k>=D, 0 at s=0)
// grid (NOUT/256, MDIM/256), 256 threads, dynamic smem.
#define MT 256
#define NT 256
#define BK 32
#define NSTAGE 3
#define A_BYTES (MT * 128)                 // 32KB
#define STAGE_BYTES (A_BYTES + NT * 128)   // 64KB
#define NK (KDIM / BK)                     // 64
#define GEMM_SMEM (NSTAGE * STAGE_BYTES + 2048)

__device__ __forceinline__ float act_sig(float x) { return 1.f / (1.f + __expf(-x)); }

#if QRNN_TC
static __device__ __forceinline__ void load_stage(int tid, int m0, int n0,
                                                  uint32_t sbase, int st, int k0) {
    uint32_t sA = sbase + st * STAGE_BYTES;
    uint32_t sB = sA + A_BYTES;
#pragma unroll
    for (int i = 0; i < 8; i++) {
        int c = tid + i * 256;
        int r = c >> 3;
        int c8 = c & 7;
        int m = m0 + r;
        int s = m >> 4;
        int b = m & 15;
        int k = k0 + c8 * 4;
        const float* src;
        int sz = 16;
        if (k < D_)      src = g_Xr + ((size_t)b * S_ + s) * D_ + k;
        else if (s > 0)  src = g_Xr + ((size_t)b * S_ + (s - 1)) * D_ + (k - D_);
        else { src = g_Xr; sz = 0; }   // zero-fill
        uint32_t off = (uint32_t)(r * 128 + c8 * 16);
        off ^= (off >> 3) & 0x70;      // SW128
        cp_async16(sA + off, src, sz);
    }
#pragma unroll
    for (int i = 0; i < 8; i++) {
        int c = tid + i * 256;
        int r = c >> 3;
        int c8 = c & 7;
        const float* src = g_Wr + (size_t)(n0 + r) * KDIM + k0 + c8 * 4;
        uint32_t off = (uint32_t)(r * 128 + c8 * 16);
        off ^= (off >> 3) & 0x70;
        cp_async16(sB + off, src, 16);
    }
}
#endif

__global__ __launch_bounds__(256, 1)
void qrnn_gemm(const float* __restrict__ bias)
{
    extern __shared__ char dyn_smem[];
#if QRNN_TC
    // ======================= tcgen05 path (sm_103a) =======================
    __shared__ uint64_t s_mbar[NSTAGE];
    __shared__ uint32_t s_tptr;
    __shared__ float s_bias[NT];

    const int tid = threadIdx.x;
    const int wid = tid >> 5;
    const int lane = tid & 31;
    const int n0 = blockIdx.x * NT;
    const int m0 = blockIdx.y * MT;

    uint32_t sbase = (smem_u32(dyn_smem) + 1023u) & ~1023u;
    uint32_t mb[NSTAGE];
#pragma unroll
    for (int s = 0; s < NSTAGE; s++) mb[s] = smem_u32(&s_mbar[s]);

    if (wid == 0) {
        asm volatile("tcgen05.alloc.cta_group::1.sync.aligned.shared::cta.b32 [%0], %1;"
                     :: "r"(smem_u32(&s_tptr)), "r"(512u) : "memory");
    }
    if (tid == 0) {
#pragma unroll
        for (int s = 0; s < NSTAGE; s++) mbar_init(mb[s], 1);
    }
    s_bias[tid] = bias[n0 + tid];
    __syncthreads();
    const uint32_t tmem = s_tptr;

    const uint32_t IDESC = (1u << 4)             // D = F32
                         | (2u << 7)             // A = TF32
                         | (2u << 10)            // B = TF32
                         | ((NT / 8) << 17)      // N
                         | ((128 / 16) << 24);   // M_atom = 128

#pragma unroll
    for (int s = 0; s < NSTAGE; s++) { load_stage(tid, m0, n0, sbase, s, s * BK); cp_commit(); }

    for (int it = 0; it < NK; ++it) {
        const int st = it % NSTAGE;
        if (it < NK - 2)       cp_wait<NSTAGE - 1>();
        else if (it == NK - 2) cp_wait<1>();
        else                   cp_wait<0>();
        asm volatile("fence.proxy.async.shared::cta;" ::: "memory");
        __syncthreads();

        if (wid == 0 && elect_one()) {
            uint32_t sA = sbase + st * STAGE_BYTES;
            uint64_t ad = make_desc(sA);
            uint64_t bd = make_desc(sA + A_BYTES);
#pragma unroll
            for (int h = 0; h < 2; h++) {
#pragma unroll
                for (int ks = 0; ks < 4; ks++) {
                    mma_tf32_ss(tmem + h * 256,
                                ad + (uint64_t)h * 1024 + ks * 2,
                                bd + ks * 2,
                                IDESC,
                                (it > 0 || ks > 0) ? 1u : 0u);
                }
            }
            asm volatile(
                "tcgen05.commit.cta_group::1.mbarrier::arrive::one.shared::cluster.b64 [%0];"
                :: "r"(mb[st]) : "memory");
        }

        const int nxt = it + NSTAGE;
        if (nxt < NK) {
            mbar_wait(mb[st], (uint32_t)((it / NSTAGE) & 1));
            load_stage(tid, m0, n0, sbase, st, nxt * BK);
            cp_commit();
        }
    }

    mbar_wait(mb[(NK - 1) % NSTAGE], (uint32_t)(((NK - 1) / NSTAGE) & 1));
    asm volatile("tcgen05.fence::after_thread_sync;" ::: "memory");

    const int half = wid >> 2;
    const int wsub = wid & 3;
    const int m = m0 + half * 128 + wsub * 32 + lane;
    float* dst = g_Y + (size_t)m * NOUT + n0;
    const int region = n0 >> 10;   // 0:Z(tanh) 1:F(sig) 2:O(sig)
    const uint32_t tbase = tmem + half * 256 + ((uint32_t)wsub << 21);

    for (int bt = 0; bt < 8; bt++) {
        uint32_t r[32];
        asm volatile(
            "tcgen05.ld.sync.aligned.32x32b.x32.b32 "
            "{%0,%1,%2,%3,%4,%5,%6,%7,%8,%9,%10,%11,%12,%13,%14,%15,"
            "%16,%17,%18,%19,%20,%21,%22,%23,%24,%25,%26,%27,%28,%29,%30,%31}, [%32];"
            : "=r"(r[0]), "=r"(r[1]), "=r"(r[2]), "=r"(r[3]), "=r"(r[4]), "=r"(r[5]),
              "=r"(r[6]), "=r"(r[7]), "=r"(r[8]), "=r"(r[9]), "=r"(r[10]), "=r"(r[11]),
              "=r"(r[12]), "=r"(r[13]), "=r"(r[14]), "=r"(r[15]), "=r"(r[16]), "=r"(r[17]),
              "=r"(r[18]), "=r"(r[19]), "=r"(r[20]), "=r"(r[21]), "=r"(r[22]), "=r"(r[23]),
              "=r"(r[24]), "=r"(r[25]), "=r"(r[26]), "=r"(r[27]), "=r"(r[28]), "=r"(r[29]),
              "=r"(r[30]), "=r"(r[31])
            : "r"(tbase + bt * 32));
        asm volatile("tcgen05.wait::ld.sync.aligned;" ::: "memory");
#pragma unroll
        for (int c = 0; c < 32; c++) {
            float v = __uint_as_float(r[c]) + s_bias[bt * 32 + c];
            float a = (region == 0) ? tanhf(v) : act_sig(v);
            r[c] = __float_as_uint(a);
        }
#pragma unroll
        for (int q = 0; q < 8; q++) {
            float4 v4 = make_float4(__uint_as_float(r[q * 4]), __uint_as_float(r[q * 4 + 1]),
                                    __uint_as_float(r[q * 4 + 2]), __uint_as_float(r[q * 4 + 3]));
            *(float4*)(dst + bt * 32 + q * 4) = v4;
        }
    }

    __syncthreads();
    if (wid == 0) {
        asm volatile("tcgen05.relinquish_alloc_permit.cta_group::1.sync.aligned;");
        asm volatile("tcgen05.dealloc.cta_group::1.sync.aligned.b32 %0, %1;"
                     :: "r"(tmem), "r"(512u));
    }
#else
    // =============== legacy mma.sync fallback (base sm_103) ===============
    // 256x256 CTA region as 4 sequential 128x128 sub-tiles (R2-proven flow).
    const int ASTRIDE = 20;
    float* sAb = (float*)dyn_smem;                       // [2][128*20]
    float* sBb = sAb + 2 * 128 * ASTRIDE;                // [2][128*20]

    const int tid  = threadIdx.x;
    const int warp = tid >> 5;
    const int lane = tid & 31;
    const int r_ = lane >> 2;
    const int cq = lane & 3;
    const int wm = (warp >> 2) * 64;
    const int wn = (warp & 3) * 32;

    for (int sub = 0; sub < 4; sub++) {
        const int m0 = blockIdx.y * 256 + (sub >> 1) * 128;
        const int n0 = blockIdx.x * 256 + (sub & 1) * 128;
        const int region = n0 >> 10;

        float acc[4][4][4];
#pragma unroll
        for (int mt = 0; mt < 4; mt++)
#pragma unroll
            for (int nt = 0; nt < 4; nt++)
#pragma unroll
                for (int r = 0; r < 4; r++) acc[mt][nt][r] = 0.f;

        auto load_st = [&](int st, int k0) {
#pragma unroll
            for (int i = 0; i < 2; i++) {
                int c = tid + i * 256;
                int row = c >> 2;
                int kc = (c & 3) * 4;
                int m = m0 + row;
                int s = m >> 4;
                int b = m & 15;
                int k = k0 + kc;
                const float* src;
                int sz = 16;
                if (k < D_)      src = g_Xr + ((size_t)b * S_ + s) * D_ + k;
                else if (s > 0)  src = g_Xr + ((size_t)b * S_ + (s - 1)) * D_ + (k - D_);
                else { src = g_Xr; sz = 0; }
                cp_async16(smem_u32(&sAb[st * 128 * ASTRIDE + row * ASTRIDE + kc]), src, sz);
            }
#pragma unroll
            for (int i = 0; i < 2; i++) {
                int c = tid + i * 256;
                int row = c >> 2;
                int kc = (c & 3) * 4;
                cp_async16(smem_u32(&sBb[st * 128 * ASTRIDE + row * ASTRIDE + kc]),
                           g_Wr + (size_t)(n0 + row) * KDIM + k0 + kc, 16);
            }
        };

        load_st(0, 0);
        cp_commit();

        const int NKL = KDIM / 16;
        for (int it = 0; it < NKL; ++it) {
            cp_wait<0>();
            __syncthreads();
            int kn = (it + 1) * 16;
            if (kn < KDIM) load_st((it + 1) & 1, kn);
            cp_commit();

            const int st = it & 1;
            const float* As = &sAb[st * 128 * ASTRIDE];
            const float* Bs = &sBb[st * 128 * ASTRIDE];
#pragma unroll
            for (int ks = 0; ks < 16; ks += 8) {
                uint32_t af[4][4], bf[4][2];
#pragma unroll
                for (int mt = 0; mt < 4; mt++) {
                    const float* base = &As[(wm + mt * 16 + r_) * ASTRIDE + ks + cq];
                    af[mt][0] = __float_as_uint(base[0]);
                    af[mt][1] = __float_as_uint(base[8 * ASTRIDE]);
                    af[mt][2] = __float_as_uint(base[4]);
                    af[mt][3] = __float_as_uint(base[8 * ASTRIDE + 4]);
                }
#pragma unroll
                for (int nt = 0; nt < 4; nt++) {
                    const float* bb = &Bs[(wn + nt * 8 + r_) * ASTRIDE + ks + cq];
                    bf[nt][0] = __float_as_uint(bb[0]);
                    bf[nt][1] = __float_as_uint(bb[4]);
                }
#pragma unroll
                for (int mt = 0; mt < 4; mt++)
#pragma unroll
                    for (int nt = 0; nt < 4; nt++)
                        mma_tf32_legacy(acc[mt][nt][0], acc[mt][nt][1], acc[mt][nt][2], acc[mt][nt][3],
                                        af[mt][0], af[mt][1], af[mt][2], af[mt][3],
                                        bf[nt][0], bf[nt][1]);
            }
            __syncthreads();
        }

#pragma unroll
        for (int mt = 0; mt < 4; mt++) {
            int mrow = m0 + wm + mt * 16 + r_;
#pragma unroll
            for (int nt = 0; nt < 4; nt++) {
                int n = n0 + wn + nt * 8 + 2 * cq;
                float2 bb = *(const float2*)&bias[n];
                float v00 = acc[mt][nt][0] + bb.x, v01 = acc[mt][nt][1] + bb.y;
                float v10 = acc[mt][nt][2] + bb.x, v11 = acc[mt][nt][3] + bb.y;
                float2 a0, a1;
                if (region == 0) {
                    a0 = make_float2(tanhf(v00), tanhf(v01));
                    a1 = make_float2(tanhf(v10), tanhf(v11));
                } else {
                    a0 = make_float2(act_sig(v00), act_sig(v01));
                    a1 = make_float2(act_sig(v10), act_sig(v11));
                }
                *(float2*)&g_Y[(size_t)mrow * NOUT + n]       = a0;
                *(float2*)&g_Y[(size_t)(mrow + 8) * NOUT + n] = a1;
            }
        }
        __syncthreads();
    }
#endif
}

// ---------------- chunked scan ----------------
__global__ __launch_bounds__(256) void qrnn_pass1()
{
    int idx = blockIdx.x * 256 + threadIdx.x;
    int ch = idx & (BH - 1);
    int chunk = idx >> 14;
    int b = ch >> 10, h = ch & 1023;
    const size_t rowStep = (size_t)B_ * NOUT;
    const float* base = g_Y + ((size_t)(chunk * CHS) * B_ + b) * NOUT + h;
    float c = 0.f, P = 1.f;
#pragma unroll 4
    for (int t = 0; t < CHS; t++) {
        const float* p = base + (size_t)t * rowStep;
        float z = p[0];
        float f = p[H_];
        c += f * (z - c);
        P *= (1.f - f);
    }
    g_cA[idx] = c;
    g_cP[idx] = P;
}

__global__ __launch_bounds__(256) void qrnn_pass2(const float* __restrict__ hidden,
                                                  float* __restrict__ out)
{
    int ch = blockIdx.x * 256 + threadIdx.x;
    float c = hidden[ch];
#pragma unroll
    for (int j = 0; j < NCH; j++) {
        g_cin[j * BH + ch] = c;
        c = g_cA[j * BH + ch] + g_cP[j * BH + ch] * c;
    }
    out[(size_t)S_ * BH + ch] = c;                 // c_last (B,H)
}

__global__ __launch_bounds__(256) void qrnn_pass3(float* __restrict__ out)
{
    int idx = blockIdx.x * 256 + threadIdx.x;
    int ch = idx & (BH - 1);
    int chunk = idx >> 14;
    int b = ch >> 10, h = ch & 1023;
    const size_t rowStep = (size_t)B_ * NOUT;
    const float* base = g_Y + ((size_t)(chunk * CHS) * B_ + b) * NOUT + h;
    float* obase = out + ((size_t)(chunk * CHS) * B_ + b) * H_ + h;
    float c = g_cin[idx];
#pragma unroll 4
    for (int t = 0; t < CHS; t++) {
        const float* p = base + (size_t)t * rowStep;
        float z = p[0];
        float f = p[H_];
        float o = p[2 * H_];
        c += f * (z - c);
        obase[(size_t)t * BH] = o * c;
    }
}

// ---------------- launch ----------------
extern "C" void kernel_launch(void* const* d_in, const int* in_sizes, int n_in,
                              void* d_out, int out_size)
{
    const float* X      = (const float*)d_in[0];
    const float* hidden = (const float*)d_in[1];
    const float* W      = (const float*)d_in[2];
    const float* bias   = (const float*)d_in[3];
    float* out = (float*)d_out;

    static bool attr_set = false;
    if (!attr_set) {
        cudaFuncSetAttribute(qrnn_gemm, cudaFuncAttributeMaxDynamicSharedMemorySize, GEMM_SMEM);
        attr_set = true;
    }

    round_x<<<4096, 256>>>((const float4*)X);
    round_w<<<6144, 256>>>((const float4*)W);

    dim3 grid(NOUT / NT, MDIM / MT);   // (12, 128); n-fastest for A-panel L2 reuse
    qrnn_gemm<<<grid, 256, GEMM_SMEM>>>(bias);

    qrnn_pass1<<<(NCH * BH) / 256, 256>>>();
    qrnn_pass2<<<BH / 256, 256>>>(hidden, out);
    qrnn_pass3<<<(NCH * BH) / 256, 256>>>(out);
}